// round 5
// baseline (speedup 1.0000x reference)
#include <cuda_runtime.h>
#include <cstdint>

#define NB_ROWS 8192
#define ND_IN   768
#define ND_HID  16384
#define K_TOP   32

// ---------------- device scratch (static, allocation-free) ----------------
__device__ float g_WdecT[(size_t)ND_HID * ND_IN];   // W_dec transposed [16384][768]
__device__ int   g_tk_idx[NB_ROWS * K_TOP];
__device__ float g_tk_val[NB_ROWS * K_TOP];

// ---------------- packed f32x2 helpers ----------------
#define FMA2(d, a, b) asm("fma.rn.f32x2 %0, %1, %2, %0;" : "+l"(d) : "l"(a), "l"(b))
#define PACK2(d, f)   asm("mov.b64 %0, {%1, %1};" : "=l"(d) : "r"(__float_as_uint(f)))

// =====================================================================
// Kernel 1: encoder GEMM  L[m,n] = relu( sum_k X[m,k] * W[n,k] )
// M=8192 N=16384 K=768. 128x128 tile, BK=8, 256 threads, 8x8/thread,
// double-buffered smem, inner loop in packed fma.rn.f32x2.
// =====================================================================
__global__ void __launch_bounds__(256, 2) enc_gemm_kernel(
    const float* __restrict__ X, const float* __restrict__ W, float* __restrict__ L)
{
    __shared__ __align__(16) float As[2][8][128];
    __shared__ __align__(16) float Bs[2][8][128];

    const int tid = threadIdx.x;
    const int m0 = blockIdx.y * 128;
    const int n0 = blockIdx.x * 128;

    const int ldRow = tid >> 1;          // 0..127
    const int ldCol = (tid & 1) << 2;    // 0 or 4
    const float* Xg = X + (size_t)(m0 + ldRow) * ND_IN + ldCol;
    const float* Wg = W + (size_t)(n0 + ldRow) * ND_IN + ldCol;

    const int tx = tid & 15;             // col group
    const int ty = tid >> 4;             // row group

    unsigned long long acc[4][8];
    #pragma unroll
    for (int i = 0; i < 4; ++i)
        #pragma unroll
        for (int j = 0; j < 8; ++j) acc[i][j] = 0ull;

    // preload tile 0
    float4 av = *(const float4*)Xg;
    float4 bv = *(const float4*)Wg;
    As[0][ldCol + 0][ldRow] = av.x; As[0][ldCol + 1][ldRow] = av.y;
    As[0][ldCol + 2][ldRow] = av.z; As[0][ldCol + 3][ldRow] = av.w;
    Bs[0][ldCol + 0][ldRow] = bv.x; Bs[0][ldCol + 1][ldRow] = bv.y;
    Bs[0][ldCol + 2][ldRow] = bv.z; Bs[0][ldCol + 3][ldRow] = bv.w;
    __syncthreads();

    int buf = 0;
    const int NT = ND_IN / 8;  // 96
    for (int t = 0; t < NT; ++t) {
        float4 av2, bv2;
        if (t + 1 < NT) {
            av2 = *(const float4*)(Xg + (t + 1) * 8);
            bv2 = *(const float4*)(Wg + (t + 1) * 8);
        }
        #pragma unroll
        for (int k = 0; k < 8; ++k) {
            // A row-pairs come packed straight out of smem (LDS.128 -> 2x f32x2)
            ulonglong2 aL = *(const ulonglong2*)&As[buf][k][ty * 4];
            ulonglong2 aH = *(const ulonglong2*)&As[buf][k][ty * 4 + 64];
            float4 bL = *(const float4*)&Bs[buf][k][tx * 4];
            float4 bH = *(const float4*)&Bs[buf][k][tx * 4 + 64];
            unsigned long long ap[4] = { aL.x, aL.y, aH.x, aH.y };
            float bf[8] = { bL.x, bL.y, bL.z, bL.w, bH.x, bH.y, bH.z, bH.w };
            unsigned long long bd[8];
            #pragma unroll
            for (int j = 0; j < 8; ++j) PACK2(bd[j], bf[j]);
            #pragma unroll
            for (int ip = 0; ip < 4; ++ip)
                #pragma unroll
                for (int j = 0; j < 8; ++j)
                    FMA2(acc[ip][j], ap[ip], bd[j]);
        }
        if (t + 1 < NT) {
            buf ^= 1;
            As[buf][ldCol + 0][ldRow] = av2.x; As[buf][ldCol + 1][ldRow] = av2.y;
            As[buf][ldCol + 2][ldRow] = av2.z; As[buf][ldCol + 3][ldRow] = av2.w;
            Bs[buf][ldCol + 0][ldRow] = bv2.x; Bs[buf][ldCol + 1][ldRow] = bv2.y;
            Bs[buf][ldCol + 2][ldRow] = bv2.z; Bs[buf][ldCol + 3][ldRow] = bv2.w;
            __syncthreads();
        }
    }

    // epilogue: relu + float4 stores
    #pragma unroll
    for (int rh = 0; rh < 2; ++rh) {
        #pragma unroll
        for (int rr = 0; rr < 4; ++rr) {
            int r = m0 + rh * 64 + ty * 4 + rr;
            int ip = rh * 2 + (rr >> 1);
            int comp = rr & 1;
            float oL[4], oH[4];
            #pragma unroll
            for (int j = 0; j < 4; ++j) {
                float2 f0 = *(float2*)&acc[ip][j];
                float2 f1 = *(float2*)&acc[ip][j + 4];
                oL[j] = fmaxf(comp ? f0.y : f0.x, 0.0f);
                oH[j] = fmaxf(comp ? f1.y : f1.x, 0.0f);
            }
            float* out = L + (size_t)r * ND_HID + n0;
            *(float4*)(out + tx * 4)      = make_float4(oL[0], oL[1], oL[2], oL[3]);
            *(float4*)(out + 64 + tx * 4) = make_float4(oH[0], oH[1], oH[2], oH[3]);
        }
    }
}

// =====================================================================
// Kernel 2: per-row top-32. One CTA (256 thr) per row, row in smem.
// Bit-bisection on float-as-uint (relu => all >= 0 => monotone bits).
// Early exit when count(>=P)==32 (no ties). Tie path matches jax
// top_k lowest-index-first semantics.
// =====================================================================
__device__ __forceinline__ int block_count_ge(const unsigned int* u, unsigned int X,
                                              int tid, int* s_red)
{
    int c = 0;
    const uint4* p = (const uint4*)u;
    #pragma unroll
    for (int i = 0; i < ND_HID / 4 / 256; ++i) {
        uint4 v = p[tid + (i << 8)];
        c += (v.x >= X) + (v.y >= X) + (v.z >= X) + (v.w >= X);
    }
    #pragma unroll
    for (int o = 16; o; o >>= 1) c += __shfl_xor_sync(0xffffffffu, c, o);
    if ((tid & 31) == 0) s_red[tid >> 5] = c;
    __syncthreads();
    int total = 0;
    #pragma unroll
    for (int w = 0; w < 8; ++w) total += s_red[w];
    __syncthreads();
    return total;
}

__global__ void __launch_bounds__(256) topk_kernel(float* __restrict__ latent)
{
    extern __shared__ unsigned int u[];   // 16384 uints (64KB dynamic)
    __shared__ int s_red[8];
    __shared__ int s_cnt[256];
    __shared__ int s_keepeq[K_TOP];
    __shared__ int s_slot;

    const int row = blockIdx.x;
    const int tid = threadIdx.x;
    float* Lrow = latent + (size_t)row * ND_HID;

    {   // load row
        uint4* u4 = (uint4*)u;
        const uint4* g4 = (const uint4*)Lrow;
        #pragma unroll
        for (int i = 0; i < ND_HID / 4 / 256; ++i) u4[tid + (i << 8)] = g4[tid + (i << 8)];
    }
    if (tid == 0) s_slot = 0;
    __syncthreads();

    unsigned int P = 0;
    bool exact = false;
    for (int bit = 30; bit >= 0 && !exact; --bit) {
        unsigned int cand = P | (1u << bit);
        int c = block_count_ge(u, cand, tid, s_red);
        if (c >= K_TOP) { P = cand; if (c == K_TOP) exact = true; }
    }

    int need_eq = 0;
    if (!exact) {
        // P == value of 32nd largest; ties exist. Keep lowest-index equals.
        int cnt_above = block_count_ge(u, P + 1, tid, s_red);
        need_eq = K_TOP - cnt_above;
        // blocked ranges preserve index order for equal-rank selection
        int base = tid * (ND_HID / 256);
        int local = 0;
        for (int i = 0; i < ND_HID / 256; ++i) local += (u[base + i] == P);
        s_cnt[tid] = local;
        __syncthreads();
        if (tid == 0) {
            int s = 0;
            for (int i = 0; i < 256; ++i) { int v = s_cnt[i]; s_cnt[i] = s; s += v; }
        }
        __syncthreads();
        int rk = s_cnt[tid];
        for (int i = 0; i < ND_HID / 256 && rk < need_eq; ++i) {
            int g = base + i;
            if (u[g] == P) { s_keepeq[rk] = g; ++rk; }
        }
        __syncthreads();
    }

    float* tkv = g_tk_val + row * K_TOP;
    int*   tki = g_tk_idx + row * K_TOP;
    for (int i = tid; i < ND_HID; i += 256) {
        unsigned int v = u[i];
        bool keep;
        if (exact)          keep = (v >= P);
        else if (v > P)     keep = true;
        else if (v == P) {
            keep = false;
            for (int e = 0; e < need_eq; ++e)
                if (s_keepeq[e] == i) { keep = true; break; }
        } else keep = false;
        float f = __uint_as_float(v);
        Lrow[i] = keep ? f : 0.0f;
        if (keep) {
            int s = atomicAdd(&s_slot, 1);
            tki[s] = i; tkv[s] = f;
        }
    }
}

// =====================================================================
// Kernel 3: transpose W_dec [768][16384] -> g_WdecT [16384][768]
// =====================================================================
__global__ void transpose_kernel(const float* __restrict__ W)
{
    __shared__ float t[32][33];
    const int tx = threadIdx.x, ty = threadIdx.y;
    const int h0 = blockIdx.x * 32;
    const int i0 = blockIdx.y * 32;
    #pragma unroll
    for (int j = ty; j < 32; j += 8)
        t[j][tx] = W[(size_t)(i0 + j) * ND_HID + h0 + tx];
    __syncthreads();
    #pragma unroll
    for (int j = ty; j < 32; j += 8)
        g_WdecT[(size_t)(h0 + j) * ND_IN + i0 + tx] = t[tx][j];
}

// =====================================================================
// Kernel 4: recon[row,:] = sum_j val_j * WdecT[idx_j, :]
// =====================================================================
__global__ void __launch_bounds__(256) recon_kernel(float* __restrict__ recon)
{
    __shared__ int   si[K_TOP];
    __shared__ float sv[K_TOP];
    const int row = blockIdx.x;
    const int tid = threadIdx.x;
    if (tid < K_TOP) {
        si[tid] = g_tk_idx[row * K_TOP + tid];
        sv[tid] = g_tk_val[row * K_TOP + tid];
    }
    __syncthreads();
    float a0 = 0.f, a1 = 0.f, a2 = 0.f;
    #pragma unroll 4
    for (int j = 0; j < K_TOP; ++j) {
        const float* w = g_WdecT + (size_t)si[j] * ND_IN;
        float v = sv[j];
        a0 += v * w[tid];
        a1 += v * w[tid + 256];
        a2 += v * w[tid + 512];
    }
    float* r = recon + (size_t)row * ND_IN;
    r[tid] = a0; r[tid + 256] = a1; r[tid + 512] = a2;
}

// =====================================================================
extern "C" void kernel_launch(void* const* d_in, const int* in_sizes, int n_in,
                              void* d_out, int out_size)
{
    (void)in_sizes; (void)n_in; (void)out_size;
    const float* x     = (const float*)d_in[0];
    const float* W_enc = (const float*)d_in[1];
    const float* W_dec = (const float*)d_in[2];
    float* latent = (float*)d_out;
    float* recon  = (float*)d_out + (size_t)NB_ROWS * ND_HID;

    // 1) dense relu latent straight into d_out
    dim3 gg(ND_HID / 128, NB_ROWS / 128);
    enc_gemm_kernel<<<gg, 256>>>(x, W_enc, latent);

    // 2) in-place top-32 sparsify + record (idx,val)
    cudaFuncSetAttribute(topk_kernel, cudaFuncAttributeMaxDynamicSharedMemorySize,
                         ND_HID * (int)sizeof(unsigned int));
    topk_kernel<<<NB_ROWS, 256, ND_HID * sizeof(unsigned int)>>>(latent);

    // 3) transpose decoder weights for coalesced gathers
    transpose_kernel<<<dim3(ND_HID / 32, ND_IN / 32), dim3(32, 8)>>>(W_dec);

    // 4) sparse decoder
    recon_kernel<<<NB_ROWS, 256>>>(recon);
}